// round 7
// baseline (speedup 1.0000x reference)
#include <cuda_runtime.h>

#define N_NODES 100000
#define N_EDGES 1600000
#define C_IN    128
#define C       64
#define HID3    256
#define SCAN_B  512
#define SCAN_NB 196   // ceil(100000/512)

// ---------------- scratch (device globals; no allocation allowed) ----------
__device__ int   g_is64;
__device__ int   g_deg[N_NODES];
__device__ float g_dinv[N_NODES];
__device__ int   g_rowptr[N_NODES + 1];
__device__ int   g_writepos[N_NODES];
__device__ int   g_blocksums[SCAN_B];
__device__ int   g_src[N_EDGES];
__device__ int   g_dst[N_EDGES];
__device__ int   g_colsrc[N_EDGES];
__device__ float g_bufA[N_NODES * C];   // GEMM outputs land here
__device__ float g_bufB[N_NODES * C];   // aggregation outputs land here
__device__ float g_Wc[C * C];           // W3@W4 folded
__device__ float g_bc[C];               // b3@W4 + b4 folded

// ---------------- dtype probe ----------------------------------------------
// int64 little-endian values < 2^31 have zero high words at odd int32 slots.
// Random int32 node indices make that astronomically unlikely.
__global__ void k_probe(const int* __restrict__ ei32) {
    if (threadIdx.x == 0) {
        int all_hi_zero = 1;
        #pragma unroll 1
        for (int i = 0; i < 256; i++)
            if (ei32[2 * i + 1] != 0) { all_hi_zero = 0; break; }
        g_is64 = all_hi_zero;
    }
}

// ---------------- graph preprocessing --------------------------------------
__global__ void k_zero_deg() {
    int i = blockIdx.x * blockDim.x + threadIdx.x;
    if (i < N_NODES) g_deg[i] = 0;
}

__global__ void k_build(const void* __restrict__ ei) {
    int e = blockIdx.x * blockDim.x + threadIdx.x;
    if (e >= N_EDGES) return;
    int s, d;
    if (g_is64) {
        const long long* p = (const long long*)ei;
        s = (int)p[e];
        d = (int)p[N_EDGES + e];
    } else {
        const int* p = (const int*)ei;
        s = p[e];
        d = p[N_EDGES + e];
    }
    if ((unsigned)s >= N_NODES || (unsigned)d >= N_NODES) { // safety net
        g_src[e] = 0; g_dst[e] = 0; atomicAdd(&g_deg[0], 1);
        return;
    }
    g_src[e] = s;
    g_dst[e] = d;
    atomicAdd(&g_deg[d], 1);
}

__global__ void k_dinv() {
    int i = blockIdx.x * blockDim.x + threadIdx.x;
    if (i < N_NODES) g_dinv[i] = rsqrtf((float)g_deg[i] + 1.0f);
}

// exclusive scan of g_deg -> g_rowptr (3-phase block scan)
__global__ void k_scan1() {
    __shared__ int sh[SCAN_B];
    int t = threadIdx.x;
    int i = blockIdx.x * SCAN_B + t;
    int v = (i < N_NODES) ? g_deg[i] : 0;
    sh[t] = v;
    __syncthreads();
    for (int off = 1; off < SCAN_B; off <<= 1) {
        int add = (t >= off) ? sh[t - off] : 0;
        __syncthreads();
        sh[t] += add;
        __syncthreads();
    }
    if (i < N_NODES) g_rowptr[i] = sh[t] - v;   // exclusive
    if (t == SCAN_B - 1) g_blocksums[blockIdx.x] = sh[t];
}

__global__ void k_scan2() {
    __shared__ int sh[SCAN_B];
    int t = threadIdx.x;
    int v = (t < SCAN_NB) ? g_blocksums[t] : 0;
    sh[t] = v;
    __syncthreads();
    for (int off = 1; off < SCAN_B; off <<= 1) {
        int add = (t >= off) ? sh[t - off] : 0;
        __syncthreads();
        sh[t] += add;
        __syncthreads();
    }
    if (t < SCAN_NB) g_blocksums[t] = sh[t] - v;  // exclusive over block sums
}

__global__ void k_scan3() {
    int i = blockIdx.x * SCAN_B + threadIdx.x;
    if (i < N_NODES) {
        int r = g_rowptr[i] + g_blocksums[blockIdx.x];
        g_rowptr[i]   = r;
        g_writepos[i] = r;
    }
    if (i == 0) g_rowptr[N_NODES] = N_EDGES;
}

__global__ void k_fill() {
    int e = blockIdx.x * blockDim.x + threadIdx.x;
    if (e >= N_EDGES) return;
    int d = g_dst[e];
    int p = atomicAdd(&g_writepos[d], 1);
    g_colsrc[p] = g_src[e];
}

// ---------------- folded linear weights ------------------------------------
__global__ void k_wc(const float* __restrict__ W3, const float* __restrict__ W4,
                     const float* __restrict__ b3, const float* __restrict__ b4) {
    int i = blockIdx.x;    // 0..63
    int c = threadIdx.x;   // 0..63
    float acc = 0.0f;
    for (int j = 0; j < HID3; j++)
        acc = fmaf(W3[i * HID3 + j], W4[j * C + c], acc);
    g_Wc[i * C + c] = acc;
    if (i == 0) {
        float accb = 0.0f;
        for (int j = 0; j < HID3; j++)
            accb = fmaf(b3[j], W4[j * C + c], accb);
        g_bc[c] = accb + b4[c];
    }
}

// ---------------- GEMM: Y[N][64] = X[N][K] @ W[K][64] (+epilogue) ----------
// MODE 0: X=ext(x, K=128),   W=ext,   Y = acc * dinv[row]   -> g_bufA
// MODE 1: X=g_bufB (K=64),   W=ext,   Y = acc * dinv[row]   -> g_bufA
// MODE 2: X=g_bufB (K=64),   W=g_Wc,  Y = acc + g_bc[col]   -> g_bufA
template <int K, int MODE>
__global__ void k_gemm(const float* __restrict__ Xext, const float* __restrict__ Wext) {
    __shared__ float Xs[32][64];
    __shared__ float Ws[64][64];
    const float* X = (MODE == 0) ? Xext : g_bufB;
    const float* W = (MODE == 2) ? g_Wc : Wext;
    float* Y = g_bufA;

    int tid = threadIdx.x;          // 128 threads
    int cg  = tid & 15;             // 16 col-groups x 4 cols
    int rg  = tid >> 4;             // 8 row-groups x 4 rows
    int row0 = blockIdx.x * 32;

    float acc[4][4] = {};

    for (int k0 = 0; k0 < K; k0 += 64) {
        #pragma unroll
        for (int idx = tid; idx < 32 * 64; idx += 128) {
            int r = idx >> 6, kk = idx & 63;
            Xs[r][kk] = X[(row0 + r) * K + k0 + kk];
        }
        #pragma unroll
        for (int idx = tid; idx < 64 * 64; idx += 128) {
            int kk = idx >> 6, c = idx & 63;
            Ws[kk][c] = W[(k0 + kk) * C + c];
        }
        __syncthreads();
        #pragma unroll 16
        for (int kk = 0; kk < 64; kk++) {
            float4 w = *(const float4*)&Ws[kk][cg * 4];
            float x0 = Xs[rg * 4 + 0][kk];
            float x1 = Xs[rg * 4 + 1][kk];
            float x2 = Xs[rg * 4 + 2][kk];
            float x3 = Xs[rg * 4 + 3][kk];
            acc[0][0] = fmaf(x0, w.x, acc[0][0]); acc[0][1] = fmaf(x0, w.y, acc[0][1]);
            acc[0][2] = fmaf(x0, w.z, acc[0][2]); acc[0][3] = fmaf(x0, w.w, acc[0][3]);
            acc[1][0] = fmaf(x1, w.x, acc[1][0]); acc[1][1] = fmaf(x1, w.y, acc[1][1]);
            acc[1][2] = fmaf(x1, w.z, acc[1][2]); acc[1][3] = fmaf(x1, w.w, acc[1][3]);
            acc[2][0] = fmaf(x2, w.x, acc[2][0]); acc[2][1] = fmaf(x2, w.y, acc[2][1]);
            acc[2][2] = fmaf(x2, w.z, acc[2][2]); acc[2][3] = fmaf(x2, w.w, acc[2][3]);
            acc[3][0] = fmaf(x3, w.x, acc[3][0]); acc[3][1] = fmaf(x3, w.y, acc[3][1]);
            acc[3][2] = fmaf(x3, w.z, acc[3][2]); acc[3][3] = fmaf(x3, w.w, acc[3][3]);
        }
        __syncthreads();
    }

    #pragma unroll
    for (int j = 0; j < 4; j++) {
        int r = row0 + rg * 4 + j;
        float4 o;
        if (MODE == 2) {
            o.x = acc[j][0] + g_bc[cg * 4 + 0];
            o.y = acc[j][1] + g_bc[cg * 4 + 1];
            o.z = acc[j][2] + g_bc[cg * 4 + 2];
            o.w = acc[j][3] + g_bc[cg * 4 + 3];
        } else {
            float s = g_dinv[r];
            o.x = acc[j][0] * s;
            o.y = acc[j][1] * s;
            o.z = acc[j][2] * s;
            o.w = acc[j][3] * s;
        }
        *(float4*)&Y[r * C + cg * 4] = o;
    }
}

// ---------------- CSR aggregation: bufB = relu(dinv*(sum+self) + b) --------
// Input g_bufA holds h_s = h * dinv (pre-scaled). One warp per node,
// lane handles 2 channels as float2. 4-way edge unroll for MLP.
__global__ void k_agg(const float* __restrict__ bias) {
    int warp = (blockIdx.x * blockDim.x + threadIdx.x) >> 5;
    int lane = threadIdx.x & 31;
    if (warp >= N_NODES) return;

    const float2* H2 = (const float2*)g_bufA;
    float2 acc = H2[warp * 32 + lane];          // self-loop term (h_s[i])
    int beg = g_rowptr[warp];
    int end = g_rowptr[warp + 1];
    int e = beg;
    for (; e + 4 <= end; e += 4) {
        int s0 = g_colsrc[e + 0];
        int s1 = g_colsrc[e + 1];
        int s2 = g_colsrc[e + 2];
        int s3 = g_colsrc[e + 3];
        float2 v0 = H2[s0 * 32 + lane];
        float2 v1 = H2[s1 * 32 + lane];
        float2 v2 = H2[s2 * 32 + lane];
        float2 v3 = H2[s3 * 32 + lane];
        acc.x += (v0.x + v1.x) + (v2.x + v3.x);
        acc.y += (v0.y + v1.y) + (v2.y + v3.y);
    }
    for (; e < end; e++) {
        int s = g_colsrc[e];
        float2 v = H2[s * 32 + lane];
        acc.x += v.x;
        acc.y += v.y;
    }
    float d = g_dinv[warp];
    float2 b = ((const float2*)bias)[lane];
    float2 o;
    o.x = fmaxf(fmaf(acc.x, d, b.x), 0.0f);
    o.y = fmaxf(fmaf(acc.y, d, b.y), 0.0f);
    ((float2*)g_bufB)[warp * 32 + lane] = o;
}

// ---------------- log_softmax over 64 channels (warp per node) -------------
__global__ void k_lsm(float* __restrict__ Out) {
    int warp = (blockIdx.x * blockDim.x + threadIdx.x) >> 5;
    int lane = threadIdx.x & 31;
    if (warp >= N_NODES) return;
    float2 y = ((const float2*)g_bufA)[warp * 32 + lane];
    float m = fmaxf(y.x, y.y);
    #pragma unroll
    for (int off = 16; off; off >>= 1)
        m = fmaxf(m, __shfl_xor_sync(0xffffffffu, m, off));
    float s = expf(y.x - m) + expf(y.y - m);
    #pragma unroll
    for (int off = 16; off; off >>= 1)
        s += __shfl_xor_sync(0xffffffffu, s, off);
    float lse = m + logf(s);
    float2 o;
    o.x = y.x - lse;
    o.y = y.y - lse;
    ((float2*)Out)[warp * 32 + lane] = o;
}

// ---------------- launch ----------------------------------------------------
extern "C" void kernel_launch(void* const* d_in, const int* in_sizes, int n_in,
                              void* d_out, int out_size) {
    const float* x  = (const float*)d_in[0];
    const void*  ei = d_in[1];
    const float* W1 = (const float*)d_in[2];
    const float* b1 = (const float*)d_in[3];
    const float* W2 = (const float*)d_in[4];
    const float* b2 = (const float*)d_in[5];
    const float* W3 = (const float*)d_in[6];
    const float* b3 = (const float*)d_in[7];
    const float* W4 = (const float*)d_in[8];
    const float* b4 = (const float*)d_in[9];
    float* out = (float*)d_out;

    const int NODE_BLK = (N_NODES + 255) / 256;
    const int EDGE_BLK = (N_EDGES + 255) / 256;
    const int WARP_BLK = (N_NODES * 32 + 255) / 256;
    const int GEMM_BLK = N_NODES / 32;   // 3125, exact

    // CSR + degree preprocessing (fixed per launch, recomputed deterministically)
    k_probe<<<1, 32>>>((const int*)ei);
    k_zero_deg<<<NODE_BLK, 256>>>();
    k_build<<<EDGE_BLK, 256>>>(ei);
    k_dinv<<<NODE_BLK, 256>>>();
    k_scan1<<<SCAN_NB, SCAN_B>>>();
    k_scan2<<<1, SCAN_B>>>();
    k_scan3<<<SCAN_NB, SCAN_B>>>();
    k_fill<<<EDGE_BLK, 256>>>();

    // Folded W3@W4 (independent; tiny)
    k_wc<<<C, C>>>(W3, W4, b3, b4);

    // Layer 1: h_s = (x@W1)*dinv ; agg+relu
    k_gemm<C_IN, 0><<<GEMM_BLK, 128>>>(x, W1);
    k_agg<<<WARP_BLK, 256>>>(b1);

    // Layer 2: h_s = (relu1@W2)*dinv ; agg+relu
    k_gemm<C, 1><<<GEMM_BLK, 128>>>(x, W2);
    k_agg<<<WARP_BLK, 256>>>(b2);

    // Folded linear: y = relu2@Wc + bc ; log_softmax
    k_gemm<C, 2><<<GEMM_BLK, 128>>>(x, W2);
    k_lsm<<<WARP_BLK, 256>>>(out);
}

// round 10
// speedup vs baseline: 1.2918x; 1.2918x over previous
#include <cuda_runtime.h>

#define N_NODES 100000
#define N_EDGES 1600000
#define C_IN    128
#define C       64
#define HID3    256
#define SCAN_B  512
#define SCAN_NB 196   // ceil(100000/512)

// ---------------- scratch (device globals; no allocation allowed) ----------
__device__ int   g_is64;
__device__ int   g_deg[N_NODES];
__device__ float g_dinv[N_NODES];
__device__ int   g_rowptr[N_NODES + 1];
__device__ int   g_writepos[N_NODES];
__device__ int   g_blocksums[SCAN_B];
__device__ int   g_colsrc[N_EDGES];
__device__ float g_bufA[N_NODES * C];   // GEMM outputs land here
__device__ float g_bufB[N_NODES * C];   // aggregation outputs land here
__device__ float g_Wc[C * C];           // W3@W4 folded
__device__ float g_bc[C];               // b3@W4 + b4 folded

// ---------------- packed f32x2 helpers (Blackwell FFMA2) --------------------
__device__ __forceinline__ unsigned long long pk2(float lo, float hi) {
    unsigned long long r;
    asm("mov.b64 %0, {%1, %2};" : "=l"(r) : "f"(lo), "f"(hi));
    return r;
}
__device__ __forceinline__ void ffma2(unsigned long long& acc,
                                      unsigned long long a, unsigned long long b) {
    asm("fma.rn.f32x2 %0, %1, %2, %3;" : "=l"(acc) : "l"(a), "l"(b), "l"(acc));
}
__device__ __forceinline__ float2 upk2(unsigned long long v) {
    float2 f;
    asm("mov.b64 {%0, %1}, %2;" : "=f"(f.x), "=f"(f.y) : "l"(v));
    return f;
}

// ---------------- zero deg + dtype probe ------------------------------------
// int64 little-endian values < 2^31 have zero high words at odd int32 slots.
__global__ void k_zero_probe(const int* __restrict__ ei32) {
    int i = blockIdx.x * blockDim.x + threadIdx.x;
    if (i < N_NODES) g_deg[i] = 0;
    if (i == 0) {
        int all_hi_zero = 1;
        #pragma unroll 1
        for (int j = 0; j < 256; j++)
            if (ei32[2 * j + 1] != 0) { all_hi_zero = 0; break; }
        g_is64 = all_hi_zero;
    }
}

__global__ void k_build(const void* __restrict__ ei) {
    int e = blockIdx.x * blockDim.x + threadIdx.x;
    if (e >= N_EDGES) return;
    int d;
    if (g_is64) {
        const long long* p = (const long long*)ei;
        int s = (int)p[e];
        d = (int)p[N_EDGES + e];
        if ((unsigned)s >= N_NODES || (unsigned)d >= N_NODES) d = 0;
    } else {
        const int* p = (const int*)ei;
        int s = p[e];
        d = p[N_EDGES + e];
        if ((unsigned)s >= N_NODES || (unsigned)d >= N_NODES) d = 0;
    }
    atomicAdd(&g_deg[d], 1);
}

// exclusive scan of g_deg -> g_rowptr (3-phase block scan); also emits dinv
__global__ void k_scan1() {
    __shared__ int sh[SCAN_B];
    int t = threadIdx.x;
    int i = blockIdx.x * SCAN_B + t;
    int v = (i < N_NODES) ? g_deg[i] : 0;
    if (i < N_NODES) g_dinv[i] = rsqrtf((float)v + 1.0f);
    sh[t] = v;
    __syncthreads();
    for (int off = 1; off < SCAN_B; off <<= 1) {
        int add = (t >= off) ? sh[t - off] : 0;
        __syncthreads();
        sh[t] += add;
        __syncthreads();
    }
    if (i < N_NODES) g_rowptr[i] = sh[t] - v;   // exclusive
    if (t == SCAN_B - 1) g_blocksums[blockIdx.x] = sh[t];
}

__global__ void k_scan2() {
    __shared__ int sh[SCAN_B];
    int t = threadIdx.x;
    int v = (t < SCAN_NB) ? g_blocksums[t] : 0;
    sh[t] = v;
    __syncthreads();
    for (int off = 1; off < SCAN_B; off <<= 1) {
        int add = (t >= off) ? sh[t - off] : 0;
        __syncthreads();
        sh[t] += add;
        __syncthreads();
    }
    if (t < SCAN_NB) g_blocksums[t] = sh[t] - v;  // exclusive over block sums
}

__global__ void k_scan3() {
    int i = blockIdx.x * SCAN_B + threadIdx.x;
    if (i < N_NODES) {
        int r = g_rowptr[i] + g_blocksums[blockIdx.x];
        g_rowptr[i]   = r;
        g_writepos[i] = r;
    }
    if (i == 0) g_rowptr[N_NODES] = N_EDGES;
}

__global__ void k_fill(const void* __restrict__ ei) {
    int e = blockIdx.x * blockDim.x + threadIdx.x;
    if (e >= N_EDGES) return;
    int s, d;
    if (g_is64) {
        const long long* p = (const long long*)ei;
        s = (int)p[e];
        d = (int)p[N_EDGES + e];
    } else {
        const int* p = (const int*)ei;
        s = p[e];
        d = p[N_EDGES + e];
    }
    if ((unsigned)s >= N_NODES || (unsigned)d >= N_NODES) { s = 0; d = 0; }
    int p2 = atomicAdd(&g_writepos[d], 1);
    g_colsrc[p2] = s;
}

// ---------------- folded linear weights ------------------------------------
__global__ void k_wc(const float* __restrict__ W3, const float* __restrict__ W4,
                     const float* __restrict__ b3, const float* __restrict__ b4) {
    int i = blockIdx.x;    // 0..63
    int c = threadIdx.x;   // 0..63
    float acc = 0.0f;
    for (int j = 0; j < HID3; j++)
        acc = fmaf(W3[i * HID3 + j], W4[j * C + c], acc);
    g_Wc[i * C + c] = acc;
    if (i == 0) {
        float accb = 0.0f;
        for (int j = 0; j < HID3; j++)
            accb = fmaf(b3[j], W4[j * C + c], accb);
        g_bc[c] = accb + b4[c];
    }
}

// ---------------- GEMM: Y[N][64] = X[N][K] @ W[K][64] (+epilogue) ----------
// MODE 0: X=ext(x, K=128),   W=ext,   Y = acc * dinv[row]   -> g_bufA
// MODE 1: X=g_bufB (K=64),   W=ext,   Y = acc * dinv[row]   -> g_bufA
// MODE 2: X=g_bufB (K=64),   W=g_Wc,  Y = acc + bc, then row log_softmax -> Out
// 128 threads: 8 row-groups x 4 rows, 16 col-groups x 4 cols (2 packed pairs).
template <int K, int MODE>
__global__ void k_gemm(const float* __restrict__ Xext, const float* __restrict__ Wext,
                       float* __restrict__ Out) {
    __shared__ float Xs[32][64];
    __shared__ float Ws[64][64];
    const float* X = (MODE == 0) ? Xext : g_bufB;
    const float* W = (MODE == 2) ? g_Wc : Wext;

    int tid = threadIdx.x;          // 128 threads
    int cg  = tid & 15;             // 16 col-groups x 4 cols
    int rg  = tid >> 4;             // 8 row-groups x 4 rows
    int row0 = blockIdx.x * 32;

    unsigned long long acc2[4][2] = {};  // [row][col-pair], packed f32x2

    for (int k0 = 0; k0 < K; k0 += 64) {
        // vectorized smem fills (float4)
        #pragma unroll
        for (int idx = tid; idx < 32 * 16; idx += 128) {
            int r = idx >> 4, kq = idx & 15;
            *(float4*)&Xs[r][kq * 4] = *(const float4*)&X[(row0 + r) * K + k0 + kq * 4];
        }
        #pragma unroll
        for (int idx = tid; idx < 64 * 16; idx += 128) {
            int kk = idx >> 4, cq = idx & 15;
            *(float4*)&Ws[kk][cq * 4] = *(const float4*)&W[(k0 + kk) * C + cq * 4];
        }
        __syncthreads();
        #pragma unroll 16
        for (int kk = 0; kk < 64; kk++) {
            ulonglong2 wp = *(const ulonglong2*)&Ws[kk][cg * 4];
            unsigned long long x0 = pk2(Xs[rg * 4 + 0][kk], Xs[rg * 4 + 0][kk]);
            unsigned long long x1 = pk2(Xs[rg * 4 + 1][kk], Xs[rg * 4 + 1][kk]);
            unsigned long long x2 = pk2(Xs[rg * 4 + 2][kk], Xs[rg * 4 + 2][kk]);
            unsigned long long x3 = pk2(Xs[rg * 4 + 3][kk], Xs[rg * 4 + 3][kk]);
            ffma2(acc2[0][0], x0, wp.x); ffma2(acc2[0][1], x0, wp.y);
            ffma2(acc2[1][0], x1, wp.x); ffma2(acc2[1][1], x1, wp.y);
            ffma2(acc2[2][0], x2, wp.x); ffma2(acc2[2][1], x2, wp.y);
            ffma2(acc2[3][0], x3, wp.x); ffma2(acc2[3][1], x3, wp.y);
        }
        __syncthreads();
    }

    if (MODE != 2) {
        #pragma unroll
        for (int j = 0; j < 4; j++) {
            int r = row0 + rg * 4 + j;
            float s = g_dinv[r];
            float2 p0 = upk2(acc2[j][0]);
            float2 p1 = upk2(acc2[j][1]);
            float4 o;
            o.x = p0.x * s; o.y = p0.y * s;
            o.z = p1.x * s; o.w = p1.y * s;
            *(float4*)&g_bufA[r * C + cg * 4] = o;
        }
    } else {
        // epilogue: +bc, stage tile into Xs (reused), then fused log_softmax
        #pragma unroll
        for (int j = 0; j < 4; j++) {
            float2 p0 = upk2(acc2[j][0]);
            float2 p1 = upk2(acc2[j][1]);
            float4 o;
            o.x = p0.x + g_bc[cg * 4 + 0];
            o.y = p0.y + g_bc[cg * 4 + 1];
            o.z = p1.x + g_bc[cg * 4 + 2];
            o.w = p1.y + g_bc[cg * 4 + 3];
            *(float4*)&Xs[rg * 4 + j][cg * 4] = o;
        }
        __syncthreads();
        int wid  = tid >> 5;   // 4 warps, 8 rows each
        int lane = tid & 31;
        #pragma unroll
        for (int j = 0; j < 8; j++) {
            int r = wid * 8 + j;
            float2 y = ((const float2*)&Xs[r][0])[lane];
            float m = fmaxf(y.x, y.y);
            #pragma unroll
            for (int off = 16; off; off >>= 1)
                m = fmaxf(m, __shfl_xor_sync(0xffffffffu, m, off));
            float se = expf(y.x - m) + expf(y.y - m);
            #pragma unroll
            for (int off = 16; off; off >>= 1)
                se += __shfl_xor_sync(0xffffffffu, se, off);
            float lse = m + logf(se);
            float2 o;
            o.x = y.x - lse;
            o.y = y.y - lse;
            ((float2*)&Out[(row0 + r) * C])[lane] = o;
        }
    }
}

// ---------------- CSR aggregation: bufB = relu(dinv*(sum+self) + b) --------
// Input g_bufA holds h_s = h * dinv (pre-scaled). One warp per node,
// lane handles 2 channels as float2. 4-way edge unroll for MLP.
__global__ void k_agg(const float* __restrict__ bias) {
    int warp = (blockIdx.x * blockDim.x + threadIdx.x) >> 5;
    int lane = threadIdx.x & 31;
    if (warp >= N_NODES) return;

    const float2* H2 = (const float2*)g_bufA;
    float2 acc = H2[warp * 32 + lane];          // self-loop term (h_s[i])
    int beg = g_rowptr[warp];
    int end = g_rowptr[warp + 1];
    int e = beg;
    for (; e + 4 <= end; e += 4) {
        int s0 = g_colsrc[e + 0];
        int s1 = g_colsrc[e + 1];
        int s2 = g_colsrc[e + 2];
        int s3 = g_colsrc[e + 3];
        float2 v0 = H2[s0 * 32 + lane];
        float2 v1 = H2[s1 * 32 + lane];
        float2 v2 = H2[s2 * 32 + lane];
        float2 v3 = H2[s3 * 32 + lane];
        acc.x += (v0.x + v1.x) + (v2.x + v3.x);
        acc.y += (v0.y + v1.y) + (v2.y + v3.y);
    }
    for (; e < end; e++) {
        int s = g_colsrc[e];
        float2 v = H2[s * 32 + lane];
        acc.x += v.x;
        acc.y += v.y;
    }
    float d = g_dinv[warp];
    float2 b = ((const float2*)bias)[lane];
    float2 o;
    o.x = fmaxf(fmaf(acc.x, d, b.x), 0.0f);
    o.y = fmaxf(fmaf(acc.y, d, b.y), 0.0f);
    ((float2*)g_bufB)[warp * 32 + lane] = o;
}

// ---------------- launch ----------------------------------------------------
extern "C" void kernel_launch(void* const* d_in, const int* in_sizes, int n_in,
                              void* d_out, int out_size) {
    const float* x  = (const float*)d_in[0];
    const void*  ei = d_in[1];
    const float* W1 = (const float*)d_in[2];
    const float* b1 = (const float*)d_in[3];
    const float* W2 = (const float*)d_in[4];
    const float* b2 = (const float*)d_in[5];
    const float* W3 = (const float*)d_in[6];
    const float* b3 = (const float*)d_in[7];
    const float* W4 = (const float*)d_in[8];
    const float* b4 = (const float*)d_in[9];
    float* out = (float*)d_out;

    const int NODE_BLK = (N_NODES + 255) / 256;
    const int EDGE_BLK = (N_EDGES + 255) / 256;
    const int WARP_BLK = (N_NODES * 32 + 255) / 256;
    const int GEMM_BLK = N_NODES / 32;   // 3125, exact

    // CSR + degree preprocessing (fixed per launch, recomputed deterministically)
    k_zero_probe<<<NODE_BLK, 256>>>((const int*)ei);
    k_build<<<EDGE_BLK, 256>>>(ei);
    k_scan1<<<SCAN_NB, SCAN_B>>>();
    k_scan2<<<1, SCAN_B>>>();
    k_scan3<<<SCAN_NB, SCAN_B>>>();
    k_fill<<<EDGE_BLK, 256>>>(ei);

    // Folded W3@W4 (independent; tiny)
    k_wc<<<C, C>>>(W3, W4, b3, b4);

    // Layer 1: h_s = (x@W1)*dinv ; agg+relu
    k_gemm<C_IN, 0><<<GEMM_BLK, 128>>>(x, W1, nullptr);
    k_agg<<<WARP_BLK, 256>>>(b1);

    // Layer 2: h_s = (relu1@W2)*dinv ; agg+relu
    k_gemm<C, 1><<<GEMM_BLK, 128>>>(x, W2, nullptr);
    k_agg<<<WARP_BLK, 256>>>(b2);

    // Folded linear + log_softmax (fused)
    k_gemm<C, 2><<<GEMM_BLK, 128>>>(x, W2, out);
}